// round 1
// baseline (speedup 1.0000x reference)
#include <cuda_runtime.h>

// Problem constants (fixed shapes from reference)
#define NMOL   256
#define NATOM  512
#define KNB    32
#define NTOT   (NMOL * NATOM)            // 131072 atoms
#define EDG    ((size_t)NTOT * KNB)      // 4194304 edges
#define TPB    128                       // threads per block (divides NATOM)
#define CAP    176                       // max candidates per atom (mean ~41, max ~150)

// Dynamic shared layout:
//   [0, 8192)                       float4 sp[NATOM]   molecule positions
//   [8192, 8192 + CAP*TPB*4)        u32 d2 keys, layout sd2[c*TPB + tid]
#define SMEM_BYTES (NATOM * 16 + CAP * TPB * 4)

__global__ void __launch_bounds__(TPB, 2)
topo_kernel(const float* __restrict__ x, float* __restrict__ out)
{
    extern __shared__ char smem[];
    float4*       sp  = (float4*)smem;
    unsigned int* sd2 = (unsigned int*)(smem + NATOM * 16);

    const int tid     = threadIdx.x;
    const int gi      = blockIdx.x * TPB + tid;      // global atom id
    const int molbase = gi & ~(NATOM - 1);           // uniform within block (TPB | NATOM)

    // Load the full molecule's positions into shared memory.
    #pragma unroll
    for (int t = tid; t < NATOM; t += TPB) {
        const int a = molbase + t;
        sp[t] = make_float4(x[3 * a + 0], x[3 * a + 1], x[3 * a + 2], 0.0f);
    }
    __syncthreads();

    const int   i  = gi & (NATOM - 1);
    const float px = sp[i].x, py = sp[i].y, pz = sp[i].z;

    // ---- Phase 1: collect candidates (0 < d2 < 1) ----
    // d2 bit pattern is a monotone u32 key for nonnegative floats.
    // Stored in j-order so that "first minimum" == lower-j tie break (lax.top_k).
    unsigned short jbuf[CAP];                        // local, tiny, L1-resident
    unsigned int*  mybuf = sd2 + tid;                // sd2[c*TPB + tid]: bank-conflict-free
    int cnt = 0;

    #pragma unroll 4
    for (int j = 0; j < NATOM; ++j) {
        const float4 q  = sp[j];
        const float  dx = q.x - px;
        const float  dy = q.y - py;
        const float  dz = q.z - pz;
        // match reference f32 arithmetic: (dx*dx + dy*dy) + dz*dz, no FMA contraction
        const float d2 = __fadd_rn(__fadd_rn(__fmul_rn(dx, dx), __fmul_rn(dy, dy)),
                                   __fmul_rn(dz, dz));
        if (d2 < 1.0f && d2 > 0.0f && cnt < CAP) {
            mybuf[cnt * TPB] = __float_as_uint(d2);
            jbuf[cnt]        = (unsigned short)j;
            ++cnt;
        }
    }

    // ---- Phase 2: K rounds of argmin with in-place invalidation ----
    unsigned int   sel_d2[KNB];
    unsigned short sel_j[KNB];
    #pragma unroll 1
    for (int r = 0; r < KNB; ++r) {
        unsigned int best = 0xFFFFFFFFu;
        int          bt   = -1;
        for (int t = 0; t < cnt; ++t) {
            const unsigned int k = mybuf[t * TPB];
            if (k < best) { best = k; bt = t; }      // strict < keeps lowest t (lowest j) on ties
        }
        if (bt >= 0) {
            mybuf[bt * TPB] = 0xFFFFFFFFu;           // remove from further rounds
            sel_j[r]        = jbuf[bt];
        } else {
            sel_j[r] = 0;
        }
        sel_d2[r] = best;
    }

    // ---- Phase 3: emit. Each atom owns 32 contiguous slots per output region,
    //      so everything goes out as full-width float4 stores. ----
    float* obi  = out + (size_t)gi * KNB;                    // bond_i
    float* obj  = out + EDG + (size_t)gi * KNB;              // bond_j
    float* ovec = out + 2 * EDG + (size_t)gi * (3 * KNB);    // vec (row-major, 96 floats/atom)
    float* odst = out + 5 * EDG + (size_t)gi * KNB;          // dist
    float* oval = out + 6 * EDG + (size_t)gi * KNB;          // valid

    const float fgi = (float)gi;

    #pragma unroll
    for (int qb = 0; qb < KNB / 4; ++qb) {
        float bi4[4], bj4[4], dd4[4], vv4[4], vec12[12];
        #pragma unroll
        for (int u = 0; u < 4; ++u) {
            const int          r  = qb * 4 + u;
            const unsigned int db = sel_d2[r];
            const bool         ok = (db != 0xFFFFFFFFu);
            const int          j  = ok ? (int)sel_j[r] : 0;
            const float4       qq = sp[j];
            vec12[u * 3 + 0] = ok ? (qq.x - px) : 0.0f;
            vec12[u * 3 + 1] = ok ? (qq.y - py) : 0.0f;
            vec12[u * 3 + 2] = ok ? (qq.z - pz) : 0.0f;
            bi4[u] = ok ? fgi : -1.0f;
            bj4[u] = ok ? (float)(molbase + j) : -1.0f;
            dd4[u] = ok ? sqrtf(__uint_as_float(db)) : 0.0f;
            vv4[u] = ok ? 1.0f : 0.0f;
        }
        *(float4*)(obi  + qb * 4)      = make_float4(bi4[0], bi4[1], bi4[2], bi4[3]);
        *(float4*)(obj  + qb * 4)      = make_float4(bj4[0], bj4[1], bj4[2], bj4[3]);
        *(float4*)(odst + qb * 4)      = make_float4(dd4[0], dd4[1], dd4[2], dd4[3]);
        *(float4*)(oval + qb * 4)      = make_float4(vv4[0], vv4[1], vv4[2], vv4[3]);
        *(float4*)(ovec + qb * 12 + 0) = make_float4(vec12[0], vec12[1], vec12[2],  vec12[3]);
        *(float4*)(ovec + qb * 12 + 4) = make_float4(vec12[4], vec12[5], vec12[6],  vec12[7]);
        *(float4*)(ovec + qb * 12 + 8) = make_float4(vec12[8], vec12[9], vec12[10], vec12[11]);
    }
}

extern "C" void kernel_launch(void* const* d_in, const int* in_sizes, int n_in,
                              void* d_out, int out_size)
{
    const float* x   = (const float*)d_in[0];   // atoms_x [NTOT, 3] float32
    float*       out = (float*)d_out;           // 7*E floats: bond_i|bond_j|vec|dist|valid

    cudaFuncSetAttribute(topo_kernel, cudaFuncAttributeMaxDynamicSharedMemorySize,
                         SMEM_BYTES);
    topo_kernel<<<NTOT / TPB, TPB, SMEM_BYTES>>>(x, out);
}

// round 2
// speedup vs baseline: 1.4402x; 1.4402x over previous
#include <cuda_runtime.h>

// Problem constants (fixed shapes from reference)
#define NMOL   256
#define NATOM  512
#define KNB    32
#define NTOT   (NMOL * NATOM)            // 131072 atoms
#define EDG    ((size_t)NTOT * KNB)      // 4194304 edges
#define TPB    128                       // threads per block (divides NATOM)
#define GSZ    16                        // tournament group size
#define NG     11                        // groups per thread
#define CAP    (GSZ * NG)                // 176 candidates max (mean ~41, max ~150)
#define INFK   0xFFFFFFFFu

// Dynamic shared layout:
//   [0, 8192)                 float4 sp[NATOM]                  molecule positions
//   [8192, +CAP*TPB*4)        u32 d2 keys, sd2[t*TPB + tid]     (strided, conflict-free)
//   [.., +NG*TPB*4)           u32 group mins, sgm[g*TPB + tid]
#define SMEM_BYTES (NATOM * 16 + CAP * TPB * 4 + NG * TPB * 4)

__global__ void __launch_bounds__(TPB, 2)
topo_kernel(const float* __restrict__ x, float* __restrict__ out)
{
    extern __shared__ char smem[];
    float4*       sp  = (float4*)smem;
    unsigned int* sd2 = (unsigned int*)(smem + NATOM * 16);
    unsigned int* sgm = (unsigned int*)(smem + NATOM * 16 + CAP * TPB * 4);

    const int tid     = threadIdx.x;
    const int gi      = blockIdx.x * TPB + tid;      // global atom id
    const int molbase = gi & ~(NATOM - 1);           // uniform within block

    #pragma unroll
    for (int t = tid; t < NATOM; t += TPB) {
        const int a = molbase + t;
        sp[t] = make_float4(x[3 * a + 0], x[3 * a + 1], x[3 * a + 2], 0.0f);
    }
    __syncthreads();

    const int   i  = gi & (NATOM - 1);
    const float px = sp[i].x, py = sp[i].y, pz = sp[i].z;

    // ---- Phase 1: collect candidates (0 < d2 < 1), j-ordered ----
    unsigned short jbuf[CAP];                        // local mem (L1-resident)
    unsigned int*  mybuf = sd2 + tid;
    unsigned int*  mygm  = sgm + tid;
    int cnt = 0;

    #pragma unroll 4
    for (int j = 0; j < NATOM; ++j) {
        const float4 q  = sp[j];
        const float  dx = q.x - px;
        const float  dy = q.y - py;
        const float  dz = q.z - pz;
        // exact reference f32 arithmetic: (dx*dx + dy*dy) + dz*dz, no contraction
        const float d2 = __fadd_rn(__fadd_rn(__fmul_rn(dx, dx), __fmul_rn(dy, dy)),
                                   __fmul_rn(dz, dz));
        if (d2 < 1.0f && d2 > 0.0f && cnt < CAP) {
            mybuf[cnt * TPB] = __float_as_uint(d2);
            jbuf[cnt]        = (unsigned short)j;
            ++cnt;
        }
    }

    // ---- Phase 1b: pad partial group with INF, build group minima ----
    const int ng  = (cnt + GSZ - 1) >> 4;
    const int pad = ng << 4;
    for (int t = cnt; t < pad; ++t) mybuf[t * TPB] = INFK;

    for (int g = 0; g < ng; ++g) {
        unsigned int v[GSZ];
        #pragma unroll
        for (int u = 0; u < GSZ; ++u) v[u] = mybuf[(g * GSZ + u) * TPB];
        #pragma unroll
        for (int s = GSZ / 2; s > 0; s >>= 1)
            #pragma unroll
            for (int u = 0; u < s; ++u) v[u] = umin(v[u], v[u + s]);
        mygm[g * TPB] = v[0];
    }
    for (int g = ng; g < NG; ++g) mygm[g * TPB] = INFK;

    // ---- Phase 2: KNB rounds of tournament argmin ----
    unsigned int   sel_d2[KNB];                      // local mem
    unsigned short sel_j[KNB];

    #pragma unroll 1
    for (int r = 0; r < KNB; ++r) {
        // scan all NG group minima (unconditional, fully unrolled, tree reduce)
        unsigned int g0[NG];
        #pragma unroll
        for (int g = 0; g < NG; ++g) g0[g] = mygm[g * TPB];
        unsigned int b0 = umin(g0[0], g0[1]);
        unsigned int b1 = umin(g0[2], g0[3]);
        unsigned int b2 = umin(g0[4], g0[5]);
        unsigned int b3 = umin(g0[6], g0[7]);
        unsigned int b4 = umin(g0[8], g0[9]);
        unsigned int best = umin(umin(umin(b0, b1), umin(b2, b3)), umin(b4, g0[10]));

        if (best != INFK) {
            int bg = 0;
            #pragma unroll
            for (int g = NG - 1; g >= 0; --g) bg = (g0[g] == best) ? g : bg;  // lowest g on tie

            const int base = bg * GSZ;
            unsigned int kv[GSZ];
            #pragma unroll
            for (int u = 0; u < GSZ; ++u) kv[u] = mybuf[(base + u) * TPB];
            int tl = 0;
            #pragma unroll
            for (int u = GSZ - 1; u >= 0; --u) tl = (kv[u] == best) ? u : tl;  // lowest t on tie

            mybuf[(base + tl) * TPB] = INFK;         // remove winner
            unsigned int w[GSZ];
            #pragma unroll
            for (int u = 0; u < GSZ; ++u) w[u] = (u == tl) ? INFK : kv[u];
            #pragma unroll
            for (int s = GSZ / 2; s > 0; s >>= 1)
                #pragma unroll
                for (int u = 0; u < s; ++u) w[u] = umin(w[u], w[u + s]);
            mygm[bg * TPB] = w[0];                   // refresh group min

            sel_d2[r] = best;
            sel_j[r]  = jbuf[base + tl];
        } else {
            sel_d2[r] = INFK;
            sel_j[r]  = 0;
        }
    }

    // ---- Phase 3: emit. Each atom owns 32 contiguous slots per region ->
    //      all 117MB goes out as full-width float4 stores. ----
    float* obi  = out + (size_t)gi * KNB;                    // bond_i
    float* obj  = out + EDG + (size_t)gi * KNB;              // bond_j
    float* ovec = out + 2 * EDG + (size_t)gi * (3 * KNB);    // vec
    float* odst = out + 5 * EDG + (size_t)gi * KNB;          // dist
    float* oval = out + 6 * EDG + (size_t)gi * KNB;          // valid

    const float fgi = (float)gi;

    #pragma unroll
    for (int qb = 0; qb < KNB / 4; ++qb) {
        float bi4[4], bj4[4], dd4[4], vv4[4], vec12[12];
        #pragma unroll
        for (int u = 0; u < 4; ++u) {
            const int          r  = qb * 4 + u;
            const unsigned int db = sel_d2[r];
            const bool         ok = (db != INFK);
            const int          j  = ok ? (int)sel_j[r] : 0;
            const float4       qq = sp[j];
            vec12[u * 3 + 0] = ok ? (qq.x - px) : 0.0f;
            vec12[u * 3 + 1] = ok ? (qq.y - py) : 0.0f;
            vec12[u * 3 + 2] = ok ? (qq.z - pz) : 0.0f;
            bi4[u] = ok ? fgi : -1.0f;
            bj4[u] = ok ? (float)(molbase + j) : -1.0f;
            dd4[u] = ok ? sqrtf(__uint_as_float(db)) : 0.0f;
            vv4[u] = ok ? 1.0f : 0.0f;
        }
        *(float4*)(obi  + qb * 4)      = make_float4(bi4[0], bi4[1], bi4[2], bi4[3]);
        *(float4*)(obj  + qb * 4)      = make_float4(bj4[0], bj4[1], bj4[2], bj4[3]);
        *(float4*)(odst + qb * 4)      = make_float4(dd4[0], dd4[1], dd4[2], dd4[3]);
        *(float4*)(oval + qb * 4)      = make_float4(vv4[0], vv4[1], vv4[2], vv4[3]);
        *(float4*)(ovec + qb * 12 + 0) = make_float4(vec12[0], vec12[1], vec12[2],  vec12[3]);
        *(float4*)(ovec + qb * 12 + 4) = make_float4(vec12[4], vec12[5], vec12[6],  vec12[7]);
        *(float4*)(ovec + qb * 12 + 8) = make_float4(vec12[8], vec12[9], vec12[10], vec12[11]);
    }
}

extern "C" void kernel_launch(void* const* d_in, const int* in_sizes, int n_in,
                              void* d_out, int out_size)
{
    const float* x   = (const float*)d_in[0];   // atoms_x [NTOT, 3] float32
    float*       out = (float*)d_out;           // 7*E floats: bond_i|bond_j|vec|dist|valid

    cudaFuncSetAttribute(topo_kernel, cudaFuncAttributeMaxDynamicSharedMemorySize,
                         SMEM_BYTES);
    topo_kernel<<<NTOT / TPB, TPB, SMEM_BYTES>>>(x, out);
}